// round 7
// baseline (speedup 1.0000x reference)
#include <cuda_runtime.h>
#include <cuda_bf16.h>

// Problem constants (fixed by dataset)
#define NN   100000
#define NE   1600000
#define BG   256
#define DIN  128
#define HH   256
#define BN_EPS 1e-5f

// ---------------------------------------------------------------------------
// Scratch (device globals; referenced ONLY inside kernel bodies)
// ---------------------------------------------------------------------------
__device__ __align__(16) float g_p1[(size_t)NN * DIN];   // aggregated x
__device__ __align__(16) float g_act1[(size_t)NN * HH];  // layer-1 act / residual
__device__ __align__(16) float g_p2[(size_t)NN * HH];    // aggregated act1
__device__ __align__(16) int2  g_edge[NE];               // CSR: (src, norm-bits)
__device__ int   g_offs[NN + 1];
__device__ int   g_cursor[NN];
__device__ int   g_hist[NN];
__device__ float g_deg[NN];
__device__ float g_dinv[NN];
__device__ float g_pool[BG * HH];
__device__ float g_cnt[BG];
__device__ float g_alpha1[HH], g_beta1[HH], g_alpha2[HH], g_beta2[HH];

__device__ __forceinline__ void red_add_v2(float* a, float x, float y) {
    asm volatile("red.global.add.v2.f32 [%0], {%1,%2};"
                 :: "l"(a), "f"(x), "f"(y) : "memory");
}

__device__ __forceinline__ void cp_async16(void* smem_dst, const void* gmem_src, bool full) {
    unsigned sa = (unsigned)__cvta_generic_to_shared(smem_dst);
    int sz = full ? 16 : 0;
    asm volatile("cp.async.ca.shared.global [%0], [%1], 16, %2;"
                 :: "r"(sa), "l"(gmem_src), "r"(sz));
}
__device__ __forceinline__ void cp_async_commit() {
    asm volatile("cp.async.commit_group;");
}

// ---------------------------------------------------------------------------
// Init + CSR build
// ---------------------------------------------------------------------------
__global__ void k_init() {
    int i = blockIdx.x * blockDim.x + threadIdx.x;
    if (i < NN) { g_deg[i] = 1.0f; g_hist[i] = 0; }
    if (i < BG * HH) g_pool[i] = 0.0f;
    if (i < BG) g_cnt[i] = 0.0f;
}

__global__ void k_bnprep(const float* __restrict__ b1, const float* __restrict__ g1,
                         const float* __restrict__ be1, const float* __restrict__ rm1,
                         const float* __restrict__ rv1,
                         const float* __restrict__ b2, const float* __restrict__ g2,
                         const float* __restrict__ be2, const float* __restrict__ rm2,
                         const float* __restrict__ rv2) {
    int c = threadIdx.x;
    float a1 = g1[c] * rsqrtf(rv1[c] + BN_EPS);
    g_alpha1[c] = a1;
    g_beta1[c] = (b1[c] - rm1[c]) * a1 + be1[c];
    float a2 = g2[c] * rsqrtf(rv2[c] + BN_EPS);
    g_alpha2[c] = a2;
    g_beta2[c] = (b2[c] - rm2[c]) * a2 + be2[c];
}

__global__ void k_edge_stats(const int* __restrict__ dst, const float* __restrict__ ew) {
    int e = blockIdx.x * blockDim.x + threadIdx.x;
    if (e < NE) {
        int d = dst[e];
        atomicAdd(&g_deg[d], ew[e]);
        atomicAdd(&g_hist[d], 1);
    }
}

// batch is sorted -> shared-mem histogram kills same-address L2-atomic serialization
__global__ __launch_bounds__(256) void k_cnt(const int* __restrict__ batch) {
    __shared__ int sh[BG];
    int t = threadIdx.x;
    sh[t] = 0;
    __syncthreads();
    int n = blockIdx.x * 256 + t;
    if (n < NN) atomicAdd_block(&sh[batch[n]], 1);
    __syncthreads();
    if (sh[t]) atomicAdd(&g_cnt[t], (float)sh[t]);
}

// Single-block exclusive scan of g_hist -> g_offs/g_cursor; also computes dinv
__global__ __launch_bounds__(1024) void k_scan() {
    __shared__ int partial[1024];
    const int CH = (NN + 1023) / 1024;
    int t = threadIdx.x;
    int lo = t * CH, hi = min(lo + CH, NN);
    int sum = 0;
    for (int i = lo; i < hi; i++) {
        sum += g_hist[i];
        g_dinv[i] = rsqrtf(g_deg[i]);
    }
    partial[t] = sum;
    __syncthreads();
    for (int off = 1; off < 1024; off <<= 1) {
        int v = (t >= off) ? partial[t - off] : 0;
        __syncthreads();
        partial[t] += v;
        __syncthreads();
    }
    int base = (t == 0) ? 0 : partial[t - 1];
    for (int i = lo; i < hi; i++) {
        int h = g_hist[i];
        g_offs[i] = base;
        g_cursor[i] = base;
        base += h;
    }
    if (t == 1023) g_offs[NN] = partial[1023];
}

__global__ void k_reorder(const int* __restrict__ src, const int* __restrict__ dst,
                          const float* __restrict__ ew) {
    int e = blockIdx.x * blockDim.x + threadIdx.x;
    if (e >= NE) return;
    int d = dst[e];
    int s = src[e];
    int pos = atomicAdd(&g_cursor[d], 1);
    float nrm = g_dinv[s] * ew[e] * g_dinv[d];
    g_edge[pos] = make_int2(s, __float_as_int(nrm));
}

// ---------------------------------------------------------------------------
// Gather: p[n] = sum_in norm_e * X[src_e] + X[n]*dinv[n]^2. Warp per node.
// ---------------------------------------------------------------------------
template <int COLS, int SRC>
__global__ __launch_bounds__(256) void k_gather(const float* __restrict__ xin) {
    int n = (blockIdx.x * blockDim.x + threadIdx.x) >> 5;
    if (n >= NN) return;
    int lane = threadIdx.x & 31;
    const float* X = SRC ? (const float*)g_act1 : xin;
    float* P = SRC ? g_p2 : g_p1;
    const int NV = COLS / 128;

    float di = g_dinv[n];
    float sc = di * di;
    const float4* xn = (const float4*)(X + (size_t)n * COLS);
    float4 acc[NV];
#pragma unroll
    for (int j = 0; j < NV; j++) {
        float4 v = __ldg(&xn[lane + j * 32]);
        acc[j] = make_float4(v.x * sc, v.y * sc, v.z * sc, v.w * sc);
    }
    int beg = g_offs[n], end = g_offs[n + 1];
    for (int e = beg; e < end; e++) {
        int2 ed = __ldg(&g_edge[e]);
        int s = ed.x;
        float w = __int_as_float(ed.y);
        const float4* xs = (const float4*)(X + (size_t)s * COLS);
#pragma unroll
        for (int j = 0; j < NV; j++) {
            float4 v = __ldg(&xs[lane + j * 32]);
            acc[j].x += w * v.x; acc[j].y += w * v.y;
            acc[j].z += w * v.z; acc[j].w += w * v.w;
        }
    }
    float4* pn = (float4*)(P + (size_t)n * COLS);
#pragma unroll
    for (int j = 0; j < NV; j++) pn[lane + j * 32] = acc[j];
}

// ---------------------------------------------------------------------------
// TF32 MMA GEMM, 2-stage cp.async double buffer. BM=128,BN=128,BK=16.
// 8 warps (2m x 4n), warp tile 64x32, m16n8k8. A/B fed raw fp32 (HW tf32 trunc).
// LAYER=1: act1 = relu(alpha1*(p1@W1)+beta1)
// LAYER=2: v = relu(alpha2*(p2@W2)+beta2)+act1; red v -> pool[batch]
// ---------------------------------------------------------------------------
template <int K, int LAYER>
__global__ __launch_bounds__(256) void k_mma(const float* __restrict__ Bm,
                                             const int* __restrict__ batch, int M) {
    const float* A = (LAYER == 1) ? g_p1 : g_p2;
    const int BM = 128, BN = 128, BK = 16;
    const int NK = K / BK;
    __shared__ __align__(16) float As[2][BM][BK + 4];   // [m][k] row-major
    __shared__ __align__(16) float Bs[2][BK][BN + 4];   // [k][n]

    int tid  = threadIdx.x;
    int wid  = tid >> 5, lane = tid & 31;
    int gid  = lane >> 2, tig = lane & 3;
    int wm   = (wid & 1) * 64;
    int wn   = (wid >> 1) * 32;
    int bm   = blockIdx.x * BM;
    int bn   = blockIdx.y * BN;

    // tile-fill coordinates (2 float4 per thread for each of A and B)
    int a_row = tid >> 1;          // 0..127 (two threads per row)
    int a_kq  = tid & 1;           // 0..1 -> k-offset 0 / 8
    int b_row = tid >> 5;          // 0..7  (first half); +8 on second pass
    int b_c4  = tid & 31;          // 0..31

    auto load_tile = [&](int kt, int buf) {
        int k0 = kt * BK;
        // A: 128 rows x 16 k = 512 float4; thread covers (a_row, a_kq*8) + (a_row, a_kq*8+4)
        {
            int gm = bm + a_row;
            bool ok = gm < M;
            const float* src = A + (size_t)gm * K + k0 + a_kq * 8;
            cp_async16(&As[buf][a_row][a_kq * 8], src, ok);
            cp_async16(&As[buf][a_row][a_kq * 8 + 4], src + 4, ok);
        }
        // B: 16 rows x 128 = 512 float4
        {
            const float* src = Bm + (size_t)(k0 + b_row) * HH + bn + b_c4 * 4;
            cp_async16(&Bs[buf][b_row][b_c4 * 4], src, true);
            src = Bm + (size_t)(k0 + b_row + 8) * HH + bn + b_c4 * 4;
            cp_async16(&Bs[buf][b_row + 8][b_c4 * 4], src, true);
        }
        cp_async_commit();
    };

    float c[4][4][4];
#pragma unroll
    for (int mf = 0; mf < 4; mf++)
#pragma unroll
        for (int nf = 0; nf < 4; nf++)
#pragma unroll
            for (int j = 0; j < 4; j++) c[mf][nf][j] = 0.f;

    load_tile(0, 0);

    for (int kt = 0; kt < NK; kt++) {
        int buf = kt & 1;
        if (kt + 1 < NK) {
            load_tile(kt + 1, buf ^ 1);
            asm volatile("cp.async.wait_group 1;");
        } else {
            asm volatile("cp.async.wait_group 0;");
        }
        __syncthreads();

#pragma unroll
        for (int ks = 0; ks < 2; ks++) {
            int kk = ks * 8;
            unsigned a[4][4], b[4][2];
#pragma unroll
            for (int mf = 0; mf < 4; mf++) {
                int r0 = wm + mf * 16 + gid;
                a[mf][0] = __float_as_uint(As[buf][r0    ][kk + tig    ]);
                a[mf][1] = __float_as_uint(As[buf][r0 + 8][kk + tig    ]);
                a[mf][2] = __float_as_uint(As[buf][r0    ][kk + tig + 4]);
                a[mf][3] = __float_as_uint(As[buf][r0 + 8][kk + tig + 4]);
            }
#pragma unroll
            for (int nf = 0; nf < 4; nf++) {
                int cc = wn + nf * 8 + gid;
                b[nf][0] = __float_as_uint(Bs[buf][kk + tig    ][cc]);
                b[nf][1] = __float_as_uint(Bs[buf][kk + tig + 4][cc]);
            }
#pragma unroll
            for (int mf = 0; mf < 4; mf++)
#pragma unroll
                for (int nf = 0; nf < 4; nf++) {
                    asm volatile(
                        "mma.sync.aligned.m16n8k8.row.col.f32.tf32.tf32.f32 "
                        "{%0,%1,%2,%3}, {%4,%5,%6,%7}, {%8,%9}, {%0,%1,%2,%3};"
                        : "+f"(c[mf][nf][0]), "+f"(c[mf][nf][1]),
                          "+f"(c[mf][nf][2]), "+f"(c[mf][nf][3])
                        : "r"(a[mf][0]), "r"(a[mf][1]), "r"(a[mf][2]), "r"(a[mf][3]),
                          "r"(b[nf][0]), "r"(b[nf][1]));
                }
        }
        __syncthreads();
    }

    // --- fused epilogue ---
#pragma unroll
    for (int nf = 0; nf < 4; nf++) {
        int cc = bn + wn + nf * 8 + tig * 2;
        float a0, a1, bb0, bb1;
        if (LAYER == 1) {
            a0 = g_alpha1[cc];  a1 = g_alpha1[cc + 1];
            bb0 = g_beta1[cc];  bb1 = g_beta1[cc + 1];
        } else {
            a0 = g_alpha2[cc];  a1 = g_alpha2[cc + 1];
            bb0 = g_beta2[cc];  bb1 = g_beta2[cc + 1];
        }
#pragma unroll
        for (int mf = 0; mf < 4; mf++) {
            int r0 = bm + wm + mf * 16 + gid;
#pragma unroll
            for (int half = 0; half < 2; half++) {
                int r = r0 + half * 8;
                if (r >= M) continue;
                float v0 = fmaxf(a0 * c[mf][nf][half * 2    ] + bb0, 0.f);
                float v1 = fmaxf(a1 * c[mf][nf][half * 2 + 1] + bb1, 0.f);
                if (LAYER == 1) {
                    *(float2*)(g_act1 + (size_t)r * HH + cc) = make_float2(v0, v1);
                } else {
                    float2 res = *(const float2*)(g_act1 + (size_t)r * HH + cc);
                    v0 += res.x; v1 += res.y;
                    int bgi = __ldg(&batch[r]);
                    red_add_v2(&g_pool[bgi * HH + cc], v0, v1);
                }
            }
        }
    }
}

// ---------------------------------------------------------------------------
// Classifier head: one block per graph, 256 threads.
// ---------------------------------------------------------------------------
__global__ __launch_bounds__(256) void k_classifier(
    const float* __restrict__ cW1, const float* __restrict__ cb1,
    const float* __restrict__ cg1, const float* __restrict__ cbe1,
    const float* __restrict__ crm1, const float* __restrict__ crv1,
    const float* __restrict__ cW2, const float* __restrict__ cb2,
    const float* __restrict__ cg2, const float* __restrict__ cbe2,
    const float* __restrict__ crm2, const float* __restrict__ crv2,
    const float* __restrict__ cW3, const float* __restrict__ cb3,
    float* __restrict__ out, int out_size) {
    __shared__ float e[256];
    __shared__ float z1[256];
    __shared__ float z2[128];
    int g = blockIdx.x, t = threadIdx.x;
    float inv = 1.0f / fmaxf(g_cnt[g], 1.0f);
    e[t] = g_pool[g * HH + t] * inv;
    __syncthreads();
    {
        float acc = cb1[t];
#pragma unroll 8
        for (int k = 0; k < 256; k++) acc += e[k] * cW1[k * 256 + t];
        acc = (acc - crm1[t]) * rsqrtf(crv1[t] + BN_EPS) * cg1[t] + cbe1[t];
        z1[t] = fmaxf(acc, 0.f);
    }
    __syncthreads();
    if (t < 128) {
        float acc = cb2[t];
#pragma unroll 8
        for (int k = 0; k < 256; k++) acc += z1[k] * cW2[k * 128 + t];
        acc = (acc - crm2[t]) * rsqrtf(crv2[t] + BN_EPS) * cg2[t] + cbe2[t];
        z2[t] = fmaxf(acc, 0.f);
    }
    __syncthreads();
    float logit = 0.f;
    if (t < 2) {
        logit = cb3[t];
#pragma unroll 8
        for (int k = 0; k < 128; k++) logit += z2[k] * cW3[k * 2 + t];
    }
    if (out_size >= 512 + BG * HH) {
        if (t < 2) out[g * 2 + t] = logit;
        out[512 + g * 256 + t] = e[t];
    } else if (out_size == BG * HH) {
        out[g * 256 + t] = e[t];
    } else {
        if (t < 2 && g * 2 + t < out_size) out[g * 2 + t] = logit;
    }
}

// ---------------------------------------------------------------------------
// Launch
// ---------------------------------------------------------------------------
extern "C" void kernel_launch(void* const* d_in, const int* in_sizes, int n_in,
                              void* d_out, int out_size) {
    const float* x    = (const float*)d_in[0];
    const int*   eidx = (const int*)d_in[1];
    const float* ew   = (const float*)d_in[2];
    const int*   batch= (const int*)d_in[3];
    const float* W1   = (const float*)d_in[4];
    const float* b1   = (const float*)d_in[5];
    const float* g1   = (const float*)d_in[6];
    const float* be1  = (const float*)d_in[7];
    const float* rm1  = (const float*)d_in[8];
    const float* rv1  = (const float*)d_in[9];
    const float* W2   = (const float*)d_in[10];
    const float* b2   = (const float*)d_in[11];
    const float* g2   = (const float*)d_in[12];
    const float* be2  = (const float*)d_in[13];
    const float* rm2  = (const float*)d_in[14];
    const float* rv2  = (const float*)d_in[15];
    const float* cW1  = (const float*)d_in[16];
    const float* cb1  = (const float*)d_in[17];
    const float* cg1  = (const float*)d_in[18];
    const float* cbe1 = (const float*)d_in[19];
    const float* crm1 = (const float*)d_in[20];
    const float* crv1 = (const float*)d_in[21];
    const float* cW2  = (const float*)d_in[22];
    const float* cb2  = (const float*)d_in[23];
    const float* cg2  = (const float*)d_in[24];
    const float* cbe2 = (const float*)d_in[25];
    const float* crm2 = (const float*)d_in[26];
    const float* crv2 = (const float*)d_in[27];
    const float* cW3  = (const float*)d_in[28];
    const float* cb3  = (const float*)d_in[29];
    float* out = (float*)d_out;

    const int* src = eidx;
    const int* dst = eidx + NE;

    // --- init + CSR build ---
    k_init<<<(NN + 255) / 256, 256>>>();
    k_bnprep<<<1, 256>>>(b1, g1, be1, rm1, rv1, b2, g2, be2, rm2, rv2);
    k_edge_stats<<<(NE + 255) / 256, 256>>>(dst, ew);
    k_cnt<<<(NN + 255) / 256, 256>>>(batch);
    k_scan<<<1, 1024>>>();
    k_reorder<<<(NE + 255) / 256, 256>>>(src, dst, ew);

    // --- layer 1 ---
    k_gather<DIN, 0><<<(NN * 32 + 255) / 256, 256>>>(x);
    {
        dim3 grid((NN + 127) / 128, HH / 128);
        k_mma<DIN, 1><<<grid, 256>>>(W1, batch, NN);
    }

    // --- layer 2 ---
    k_gather<HH, 1><<<(NN * 32 + 255) / 256, 256>>>(x /*unused*/);
    {
        dim3 grid((NN + 127) / 128, HH / 128);
        k_mma<HH, 2><<<grid, 256>>>(W2, batch, NN);
    }

    // --- head ---
    k_classifier<<<BG, 256>>>(cW1, cb1, cg1, cbe1, crm1, crv1,
                              cW2, cb2, cg2, cbe2, crm2, crv2,
                              cW3, cb3, out, out_size);
}